// round 9
// baseline (speedup 1.0000x reference)
#include <cuda_runtime.h>
#include <cuda_fp16.h>
#include <cstdint>

// ---------------- problem constants ----------------
#define BATCH 128
#define CH    256
#define TT    30
#define WW    11
#define HW    176
#define NBINS 31
#define RED   16
#define KDIM  4096
#define OUT   256
#define NCLS  10000
#define NB    (NBINS*BATCH)

#define LDA   136   // GEMM A smem row stride (fp16)
#define LDB   72    // GEMM B smem row stride (fp16)

// ---------------- scratch ----------------
__device__ float g_p[(size_t)NBINS*BATCH*TT*CH];
__device__ float g_pmax[NBINS*BATCH*CH];
__device__ __half g_pooled_hi[(size_t)NBINS*BATCH*KDIM];
__device__ __half g_pooled_lo[(size_t)NBINS*BATCH*KDIM];
__device__ __half g_feat_hi[NBINS*BATCH*CH];
__device__ __half g_feat_lo[NBINS*BATCH*CH];
__device__ __half g_bn[NBINS*BATCH*OUT];                   // fp16 single
__device__ float g_invrn[NB];
__device__ float g_rowsq[8][NB];
__device__ float g_part[(size_t)2*NBINS*BATCH*OUT];

// ---------------- helpers ----------------
__device__ __forceinline__ uint32_t smem_u32(const void* p) {
    uint32_t a;
    asm("{ .reg .u64 t; cvta.to.shared.u64 t, %1; cvt.u32.u64 %0, t; }" : "=r"(a) : "l"(p));
    return a;
}
__device__ __forceinline__ void cpa16(uint32_t dst, const void* src) {
    asm volatile("cp.async.cg.shared.global [%0], [%1], 16;" :: "r"(dst), "l"(src));
}
#define CPA_COMMIT() asm volatile("cp.async.commit_group;" ::: "memory")
#define CPA_WAIT0()  asm volatile("cp.async.wait_group 0;" ::: "memory")

__device__ __forceinline__ void ldsm4(uint32_t a[4], uint32_t addr) {
    asm volatile("ldmatrix.sync.aligned.m8n8.x4.shared.b16 {%0,%1,%2,%3}, [%4];"
        : "=r"(a[0]),"=r"(a[1]),"=r"(a[2]),"=r"(a[3]) : "r"(addr));
}
__device__ __forceinline__ void ldsm4t(uint32_t a[4], uint32_t addr) {
    asm volatile("ldmatrix.sync.aligned.m8n8.x4.trans.shared.b16 {%0,%1,%2,%3}, [%4];"
        : "=r"(a[0]),"=r"(a[1]),"=r"(a[2]),"=r"(a[3]) : "r"(addr));
}
__device__ __forceinline__ void mma_f16(float d[4], const uint32_t a[4], uint32_t b0, uint32_t b1) {
    asm volatile("mma.sync.aligned.m16n8k16.row.col.f32.f16.f16.f32 "
        "{%0,%1,%2,%3}, {%4,%5,%6,%7}, {%8,%9}, {%0,%1,%2,%3};"
        : "+f"(d[0]),"+f"(d[1]),"+f"(d[2]),"+f"(d[3])
        : "r"(a[0]),"r"(a[1]),"r"(a[2]),"r"(a[3]), "r"(b0),"r"(b1));
}
__device__ __forceinline__ unsigned pack2h(float a, float b) {
    __half2 h = __floats2half2_rn(a, b);
    return *reinterpret_cast<unsigned*>(&h);
}
__device__ __forceinline__ unsigned long long pack4h(float a, float b, float c, float d) {
    return ((unsigned long long)pack2h(c, d) << 32) | pack2h(a, b);
}
__device__ __forceinline__ float h_lo(float v) {
    return v - __half2float(__float2half_rn(v));
}

// single-pass fp16 tile step (k6).
template<int MI, int NF>
__device__ __forceinline__ void mma_tile1(uint32_t sA, uint32_t sB,
                                          int lane, int warp_m, int warp_n,
                                          float (&acc)[MI][NF][4]) {
    const int l15 = lane & 15;
    const int l16 = (lane >> 4) << 3;
    #pragma unroll
    for (int ks = 0; ks < 8; ++ks) {
        const int k = ks * 16;
        uint32_t aa[MI][4], bb[NF][2];
        #pragma unroll
        for (int mi = 0; mi < MI; ++mi)
            ldsm4(aa[mi], sA + ((warp_m + mi*16 + l15)*LDA + k + l16) * 2);
        #pragma unroll
        for (int q = 0; q < NF/2; ++q) {
            uint32_t r[4];
            ldsm4t(r, sB + ((k + l15)*LDB + warp_n + q*16 + l16) * 2);
            bb[2*q][0] = r[0]; bb[2*q][1] = r[1];
            bb[2*q+1][0] = r[2]; bb[2*q+1][1] = r[3];
        }
        #pragma unroll
        for (int mi = 0; mi < MI; ++mi)
            #pragma unroll
            for (int nf = 0; nf < NF; ++nf)
                mma_f16(acc[mi][nf], aa[mi], bb[nf][0], bb[nf][1]);
    }
}

// two-pass (A hi/lo) tile step (k3, k4).
template<int MI, int NF>
__device__ __forceinline__ void mma_tile2(uint32_t sAhi, uint32_t sAlo, uint32_t sB,
                                          int lane, int warp_m, int warp_n,
                                          float (&acc)[MI][NF][4]) {
    const int l15 = lane & 15;
    const int l16 = (lane >> 4) << 3;
    #pragma unroll
    for (int ks = 0; ks < 8; ++ks) {
        const int k = ks * 16;
        uint32_t ahi[MI][4], alo[MI][4], bb[NF][2];
        #pragma unroll
        for (int mi = 0; mi < MI; ++mi) {
            uint32_t ao = ((warp_m + mi*16 + l15)*LDA + k + l16) * 2;
            ldsm4(ahi[mi], sAhi + ao);
            ldsm4(alo[mi], sAlo + ao);
        }
        #pragma unroll
        for (int q = 0; q < NF/2; ++q) {
            uint32_t r[4];
            ldsm4t(r, sB + ((k + l15)*LDB + warp_n + q*16 + l16) * 2);
            bb[2*q][0] = r[0]; bb[2*q][1] = r[1];
            bb[2*q+1][0] = r[2]; bb[2*q+1][1] = r[3];
        }
        #pragma unroll
        for (int mi = 0; mi < MI; ++mi)
            #pragma unroll
            for (int nf = 0; nf < NF; ++nf) {
                mma_f16(acc[mi][nf], ahi[mi], bb[nf][0], bb[nf][1]);
                mma_f16(acc[mi][nf], alo[mi], bb[nf][0], bb[nf][1]);
            }
    }
}

// =====================================================================
// K1: horizontal strip pooling.
// =====================================================================
__global__ __launch_bounds__(512) void k1_hmap(const float* __restrict__ x) {
    int bid = blockIdx.x;
    int cg = bid & 7;
    int t  = (bid >> 3) % TT;
    int b  = bid / (TT * 8);

    __shared__ float xs[32][180];
    __shared__ float rsum[32][16];
    __shared__ float rmax[32][16];

    const float* xb = x + (((size_t)b*CH + cg*32)*TT + t) * HW;
    int tid = threadIdx.x;

    for (int idx = tid; idx < 32*44; idx += 512) {
        int c = idx / 44, e = idx % 44;
        float4 v = *reinterpret_cast<const float4*>(xb + (size_t)c*TT*HW + e*4);
        *reinterpret_cast<float4*>(&xs[c][e*4]) = v;
    }
    __syncthreads();
    {
        int c = tid >> 4, h = tid & 15;
        float s = 0.f, m = -1e30f;
        #pragma unroll
        for (int w = 0; w < WW; ++w) {
            float v = xs[c][h*WW + w];
            s += v; m = fmaxf(m, v);
        }
        rsum[c][h] = s; rmax[c][h] = m;
    }
    __syncthreads();

    for (int oi = tid; oi < NBINS*32; oi += 512) {
        int n = oi >> 5;
        int c = oi & 31;
        int start, len;
        if      (n == 0) { start = 0;          len = 16; }
        else if (n < 3)  { start = (n-1)*8;    len = 8;  }
        else if (n < 7)  { start = (n-3)*4;    len = 4;  }
        else if (n < 15) { start = (n-7)*2;    len = 2;  }
        else             { start = n-15;       len = 1;  }
        float s = 0.f, m = -1e30f;
        for (int h = 0; h < len; ++h) {
            s += rsum[c][start+h];
            m = fmaxf(m, rmax[c][start+h]);
        }
        g_p[(((size_t)n*BATCH + b)*TT + t)*CH + cg*32 + c] = s / (float)(len*WW) + m;
    }
}

// =====================================================================
// K2 (HMMA): logits = p@Wmask (fp16 3-pass, exact), softmax over T,
// pooled^T = maskT @ p (fp16 3-pass), pmax. 256 threads, 8 warps.
// =====================================================================
#define LDPS 264
#define LDW  24
#define LDMT 40
#define P2_PSHI 0
#define P2_PSLO (P2_PSHI + 32*LDPS*2)      // 16896
#define P2_WMHI (P2_PSLO + 32*LDPS*2)      // 33792
#define P2_WMLO (P2_WMHI + 256*LDW*2)      // 46080
#define P2_PART (P2_WMLO + 256*LDW*2)      // 58368
#define P2_LG   (P2_PART + 8*512*4)        // 74752
#define P2_MTHI (P2_LG + 512*4)            // 76800
#define P2_MTLO (P2_MTHI + 16*LDMT*2)      // 78080
#define K2_SMEM (P2_MTLO + 16*LDMT*2)      // 79360

__global__ __launch_bounds__(256, 2) void k2_mask(const float* __restrict__ Wmask) {
    extern __shared__ char smem[];
    const int nb = blockIdx.x;
    const int n = nb >> 7, b = nb & 127;
    const int tid = threadIdx.x;
    const int lane = tid & 31, wid = tid >> 5;
    const uint32_t sb = smem_u32(smem);

    __half* psHi = reinterpret_cast<__half*>(smem + P2_PSHI);
    __half* psLo = reinterpret_cast<__half*>(smem + P2_PSLO);
    float*  part = reinterpret_cast<float*>(smem + P2_PART);
    float*  lg   = reinterpret_cast<float*>(smem + P2_LG);
    __half* mtHi = reinterpret_cast<__half*>(smem + P2_MTHI);
    __half* mtLo = reinterpret_cast<__half*>(smem + P2_MTLO);

    // ---- load p -> psHi/Lo (fp16 hi/lo) ----
    const float* pg = g_p + ((size_t)n*BATCH + b)*TT*CH;
    for (int i = tid; i < TT*64; i += 256) {
        int t = i >> 6, c4 = (i & 63) * 4;
        float4 v = *reinterpret_cast<const float4*>(pg + t*CH + c4);
        int o = t*LDPS + c4;
        *reinterpret_cast<unsigned long long*>(psHi + o) = pack4h(v.x, v.y, v.z, v.w);
        *reinterpret_cast<unsigned long long*>(psLo + o) =
            pack4h(h_lo(v.x), h_lo(v.y), h_lo(v.z), h_lo(v.w));
    }
    // zero rows 30,31
    for (int i = tid; i < 2*LDPS; i += 256) {
        int t = 30 + (i >= LDPS), c = (i >= LDPS) ? i - LDPS : i;
        psHi[t*LDPS + c] = __half(0.f);
        psLo[t*LDPS + c] = __half(0.f);
    }
    // ---- load Wmask -> wmHi/Lo ----
    {
        const float* wg = Wmask + (size_t)n*CH*RED;
        __half* wmHi = reinterpret_cast<__half*>(smem + P2_WMHI);
        __half* wmLo = reinterpret_cast<__half*>(smem + P2_WMLO);
        for (int i = tid; i < CH*4; i += 256) {
            int c = i >> 2, r4 = (i & 3) * 4;
            float4 v = *reinterpret_cast<const float4*>(wg + c*RED + r4);
            int o = c*LDW + r4;
            *reinterpret_cast<unsigned long long*>(wmHi + o) = pack4h(v.x, v.y, v.z, v.w);
            *reinterpret_cast<unsigned long long*>(wmLo + o) =
                pack4h(h_lo(v.x), h_lo(v.y), h_lo(v.z), h_lo(v.w));
        }
    }
    __syncthreads();

    // ---- pmax (independent of logits) ----
    {
        int c = tid;
        float pm = -1e30f;
        for (int t = 0; t < TT; ++t)
            pm = fmaxf(pm, __half2float(psHi[t*LDPS + c]) + __half2float(psLo[t*LDPS + c]));
        g_pmax[((size_t)n*BATCH + b)*CH + c] = pm;
    }

    // ---- logits GEMM: warp wid owns K-slice [wid*32, +32) ----
    {
        float acc[2][2][4];
        #pragma unroll
        for (int mi = 0; mi < 2; ++mi)
            #pragma unroll
            for (int nf = 0; nf < 2; ++nf)
                #pragma unroll
                for (int j = 0; j < 4; ++j) acc[mi][nf][j] = 0.f;
        const int l15 = lane & 15, l16 = (lane >> 4) << 3;
        const uint32_t aHi = sb + P2_PSHI, aLo = sb + P2_PSLO;
        const uint32_t bHi = sb + P2_WMHI, bLo = sb + P2_WMLO;
        #pragma unroll
        for (int ks = 0; ks < 2; ++ks) {
            int k = wid*32 + ks*16;
            uint32_t ah[2][4], al[2][4], bh[2][2], bl[2][2], r[4];
            ldsm4(ah[0], aHi + ((0  + l15)*LDPS + k + l16)*2);
            ldsm4(ah[1], aHi + ((16 + l15)*LDPS + k + l16)*2);
            ldsm4(al[0], aLo + ((0  + l15)*LDPS + k + l16)*2);
            ldsm4(al[1], aLo + ((16 + l15)*LDPS + k + l16)*2);
            ldsm4t(r, bHi + ((k + l15)*LDW + l16)*2);
            bh[0][0]=r[0]; bh[0][1]=r[1]; bh[1][0]=r[2]; bh[1][1]=r[3];
            ldsm4t(r, bLo + ((k + l15)*LDW + l16)*2);
            bl[0][0]=r[0]; bl[0][1]=r[1]; bl[1][0]=r[2]; bl[1][1]=r[3];
            #pragma unroll
            for (int mi = 0; mi < 2; ++mi)
                #pragma unroll
                for (int nf = 0; nf < 2; ++nf) {
                    mma_f16(acc[mi][nf], ah[mi], bh[nf][0], bh[nf][1]);
                    mma_f16(acc[mi][nf], al[mi], bh[nf][0], bh[nf][1]);
                    mma_f16(acc[mi][nf], ah[mi], bl[nf][0], bl[nf][1]);
                }
        }
        const int g = lane >> 2, t2 = (lane & 3) * 2;
        #pragma unroll
        for (int mi = 0; mi < 2; ++mi)
            #pragma unroll
            for (int nf = 0; nf < 2; ++nf)
                #pragma unroll
                for (int h = 0; h < 2; ++h) {
                    int m = mi*16 + g + h*8;
                    int r0 = nf*8 + t2;
                    part[wid*512 + m*16 + r0]     = acc[mi][nf][h*2];
                    part[wid*512 + m*16 + r0 + 1] = acc[mi][nf][h*2+1];
                }
    }
    __syncthreads();

    // ---- reduce partials -> lg ----
    for (int i = tid; i < 512; i += 256) {
        float s = 0.f;
        #pragma unroll
        for (int w = 0; w < 8; ++w) s += part[w*512 + i];
        lg[i] = s;
    }
    __syncthreads();

    // ---- softmax over t (t<30), write maskT hi/lo ----
    if (tid < RED) {
        int r = tid;
        float m = -1e30f;
        for (int t = 0; t < TT; ++t) m = fmaxf(m, lg[t*16 + r]);
        float s = 0.f;
        for (int t = 0; t < TT; ++t) { float e = expf(lg[t*16 + r] - m); lg[t*16 + r] = e; s += e; }
        float inv = 1.f / s;
        for (int t = 0; t < TT; ++t) {
            float mv = lg[t*16 + r] * inv;
            __half hh = __float2half_rn(mv);
            mtHi[r*LDMT + t] = hh;
            mtLo[r*LDMT + t] = __float2half_rn(mv - __half2float(hh));
        }
        mtHi[r*LDMT + 30] = __half(0.f); mtHi[r*LDMT + 31] = __half(0.f);
        mtLo[r*LDMT + 30] = __half(0.f); mtLo[r*LDMT + 31] = __half(0.f);
    }
    __syncthreads();

    // ---- pooled^T GEMM: D[r 16][c 256]; warp wid owns c-slice [wid*32,+32) ----
    {
        float acc[4][4];
        #pragma unroll
        for (int nf = 0; nf < 4; ++nf)
            #pragma unroll
            for (int j = 0; j < 4; ++j) acc[nf][j] = 0.f;
        const int l15 = lane & 15, l16 = (lane >> 4) << 3;
        const int c0 = wid * 32;
        const uint32_t aHi = sb + P2_MTHI, aLo = sb + P2_MTLO;
        const uint32_t bHi = sb + P2_PSHI, bLo = sb + P2_PSLO;
        #pragma unroll
        for (int ks = 0; ks < 2; ++ks) {
            int k = ks * 16;
            uint32_t ah[4], al[4];
            ldsm4(ah, aHi + (l15*LDMT + k + l16)*2);
            ldsm4(al, aLo + (l15*LDMT + k + l16)*2);
            uint32_t bh[4][2], bl[4][2], r[4];
            #pragma unroll
            for (int q = 0; q < 2; ++q) {
                ldsm4t(r, bHi + ((k + l15)*LDPS + c0 + q*16 + l16)*2);
                bh[2*q][0]=r[0]; bh[2*q][1]=r[1]; bh[2*q+1][0]=r[2]; bh[2*q+1][1]=r[3];
                ldsm4t(r, bLo + ((k + l15)*LDPS + c0 + q*16 + l16)*2);
                bl[2*q][0]=r[0]; bl[2*q][1]=r[1]; bl[2*q+1][0]=r[2]; bl[2*q+1][1]=r[3];
            }
            #pragma unroll
            for (int nf = 0; nf < 4; ++nf) {
                mma_f16(acc[nf], ah, bh[nf][0], bh[nf][1]);
                mma_f16(acc[nf], al, bh[nf][0], bh[nf][1]);
                mma_f16(acc[nf], ah, bl[nf][0], bl[nf][1]);
            }
        }
        // write pooled hi/lo: element (c, r) at offset c*16 + r
        __half* dh = g_pooled_hi + ((size_t)n*BATCH + b)*KDIM;
        __half* dl = g_pooled_lo + ((size_t)n*BATCH + b)*KDIM;
        const int g = lane >> 2, t2 = (lane & 3) * 2;
        #pragma unroll
        for (int nf = 0; nf < 4; ++nf)
            #pragma unroll
            for (int h = 0; h < 2; ++h)
                #pragma unroll
                for (int j = 0; j < 2; ++j) {
                    int c = c0 + nf*8 + t2 + j;
                    int r = g + h*8;
                    float v = acc[nf][h*2 + j];
                    __half hh = __float2half_rn(v);
                    dh[c*16 + r] = hh;
                    dl[c*16 + r] = __float2half_rn(v - __half2float(hh));
                }
    }
}

// =====================================================================
// K3 (fp16x2 A, split-K=2, pipelined): partial = pooled @ Wout
// BM=128, BN=64. grid (4 N, NBINS, 2 Ksplit) = 248 CTAs, occ 2.
// =====================================================================
#define ATILE (128*LDA*2)          // 34816
#define BTILE (128*LDB*2)          // 18432
#define K3_SMEM  (2*ATILE + BTILE) // 88064

__global__ __launch_bounds__(256, 2) void k3_mma(const float* __restrict__ Wout) {
    extern __shared__ char smem[];
    const int n    = blockIdx.y;
    const int n0   = blockIdx.x * 64;
    const int ksp  = blockIdx.z;
    const int kbase = ksp * 2048;
    const int tid = threadIdx.x;
    const int lane = tid & 31, wid = tid >> 5;
    const int warp_m = (wid >> 1) * 32, warp_n = (wid & 1) * 32;
    const uint32_t sb = smem_u32(smem);
    const uint32_t sAhi = sb, sAlo = sb + ATILE, sB = sb + 2*ATILE;

    const __half* Ah = g_pooled_hi + (size_t)n*BATCH*KDIM;
    const __half* Al = g_pooled_lo + (size_t)n*BATCH*KDIM;
    const float* B = Wout + (size_t)n*KDIM*OUT;

    float acc[2][4][4];
    #pragma unroll
    for (int mi = 0; mi < 2; ++mi)
        #pragma unroll
        for (int nf = 0; nf < 4; ++nf)
            #pragma unroll
            for (int j = 0; j < 4; ++j) acc[mi][nf][j] = 0.f;

    const int cg = (tid & 15) * 4;
    const int kr = tid >> 4;
    const int arow = tid >> 4, ac8 = (tid & 15) * 8;

    float4 rB[8];
    #pragma unroll
    for (int i = 0; i < 8; ++i)
        rB[i] = *reinterpret_cast<const float4*>(B + (size_t)(kbase + kr + i*16)*OUT + n0 + cg);

    for (int kc = 0; kc < 16; ++kc) {
        #pragma unroll
        for (int i = 0; i < 8; ++i) {
            int row = arow + i*16;
            size_t gA = (size_t)row*KDIM + kbase + kc*128 + ac8;
            uint32_t so = (uint32_t)(row*LDA + ac8) * 2;
            cpa16(sAhi + so, Ah + gA);
            cpa16(sAlo + so, Al + gA);
        }
        CPA_COMMIT();
        #pragma unroll
        for (int i = 0; i < 8; ++i) {
            float4 v = rB[i];
            int o = ((kr + i*16)*LDB + cg) * 2;
            *reinterpret_cast<unsigned long long*>(smem + 2*ATILE + o) =
                pack4h(v.x, v.y, v.z, v.w);
        }
        CPA_WAIT0();
        __syncthreads();
        if (kc + 1 < 16) {
            #pragma unroll
            for (int i = 0; i < 8; ++i)
                rB[i] = *reinterpret_cast<const float4*>(
                    B + (size_t)(kbase + (kc+1)*128 + kr + i*16)*OUT + n0 + cg);
        }
        mma_tile2<2,4>(sAhi, sAlo, sB, lane, warp_m, warp_n, acc);
        __syncthreads();
    }

    float* pp = g_part + ((size_t)ksp*NBINS + n)*BATCH*OUT;
    const int g = lane >> 2, t2 = (lane & 3) * 2;
    #pragma unroll
    for (int mi = 0; mi < 2; ++mi) {
        #pragma unroll
        for (int nf = 0; nf < 4; ++nf) {
            int col = n0 + warp_n + nf*8 + t2;
            #pragma unroll
            for (int h = 0; h < 2; ++h) {
                int row = warp_m + mi*16 + g + h*8;
                *reinterpret_cast<float2*>(pp + (size_t)row*OUT + col) =
                    make_float2(acc[mi][nf][2*h], acc[mi][nf][2*h+1]);
            }
        }
    }
}

// K3 epilogue: feat = pmax + leaky(part0+part1) -> fp16 hi/lo.
__global__ __launch_bounds__(256) void k3e_epi() {
    int i4 = blockIdx.x * 256 + threadIdx.x;   // < 253952
    const float4* p0 = reinterpret_cast<const float4*>(g_part);
    const float4* p1 = reinterpret_cast<const float4*>(g_part + (size_t)NBINS*BATCH*OUT);
    const float4* pm = reinterpret_cast<const float4*>(g_pmax);
    float4 a = p0[i4], b = p1[i4], m = pm[i4];
    float o[4];
    float s;
    s = a.x + b.x; o[0] = ((s >= 0.f) ? s : 0.01f*s) + m.x;
    s = a.y + b.y; o[1] = ((s >= 0.f) ? s : 0.01f*s) + m.y;
    s = a.z + b.z; o[2] = ((s >= 0.f) ? s : 0.01f*s) + m.z;
    s = a.w + b.w; o[3] = ((s >= 0.f) ? s : 0.01f*s) + m.w;
    reinterpret_cast<unsigned long long*>(g_feat_hi)[i4] = pack4h(o[0], o[1], o[2], o[3]);
    reinterpret_cast<unsigned long long*>(g_feat_lo)[i4] =
        pack4h(h_lo(o[0]), h_lo(o[1]), h_lo(o[2]), h_lo(o[3]));
}

// =====================================================================
// K4 (fp16x2 + fused BatchNorm): outputs = feat @ FForward.
// =====================================================================
#define K4_SMEM  (2*ATILE + BTILE)     // 88064

__global__ __launch_bounds__(256, 2) void k4_ff(const float* __restrict__ FF,
                                                const float* __restrict__ gamma,
                                                const float* __restrict__ beta,
                                                float* __restrict__ out1) {
    extern __shared__ char smem[];
    const int n  = blockIdx.y;
    const int n0 = blockIdx.x * 64;
    const int tid = threadIdx.x;
    const int lane = tid & 31, wid = tid >> 5;
    const int warp_m = (wid >> 1) * 32, warp_n = (wid & 1) * 32;
    const uint32_t sb = smem_u32(smem);
    const uint32_t sAhi = sb, sAlo = sb + ATILE, sB = sb + 2*ATILE;

    const __half* Ah = g_feat_hi + (size_t)n*BATCH*CH;
    const __half* Al = g_feat_lo + (size_t)n*BATCH*CH;
    const float* B = FF + (size_t)n*CH*OUT;

    float acc[2][4][4];
    #pragma unroll
    for (int mi = 0; mi < 2; ++mi)
        #pragma unroll
        for (int nf = 0; nf < 4; ++nf)
            #pragma unroll
            for (int j = 0; j < 4; ++j) acc[mi][nf][j] = 0.f;

    const int cg = (tid & 15) * 4;
    const int kr = tid >> 4;
    const int arow = tid >> 4, ac8 = (tid & 15) * 8;

    float4 rB[8];
    #pragma unroll
    for (int i = 0; i < 8; ++i)
        rB[i] = *reinterpret_cast<const float4*>(B + (size_t)(kr + i*16)*OUT + n0 + cg);

    for (int kc = 0; kc < 2; ++kc) {
        #pragma unroll
        for (int i = 0; i < 8; ++i) {
            int row = arow + i*16;
            size_t gA = (size_t)row*CH + kc*128 + ac8;
            uint32_t so = (uint32_t)(row*LDA + ac8) * 2;
            cpa16(sAhi + so, Ah + gA);
            cpa16(sAlo + so, Al + gA);
        }
        CPA_COMMIT();
        #pragma unroll
        for (int i = 0; i < 8; ++i) {
            float4 v = rB[i];
            int o = ((kr + i*16)*LDB + cg) * 2;
            *reinterpret_cast<unsigned long long*>(smem + 2*ATILE + o) =
                pack4h(v.x, v.y, v.z, v.w);
        }
        CPA_WAIT0();
        __syncthreads();
        if (kc == 0) {
            #pragma unroll
            for (int i = 0; i < 8; ++i)
                rB[i] = *reinterpret_cast<const float4*>(
                    B + (size_t)(128 + kr + i*16)*OUT + n0 + cg);
        }
        mma_tile2<2,4>(sAhi, sAlo, sB, lane, warp_m, warp_n, acc);
        __syncthreads();
    }

    // ---- fused BatchNorm epilogue ----
    float* ob = reinterpret_cast<float*>(smem);        // [128][65]
    float* smean = ob + 128*65;
    float* sistd = smean + 64;
    const int g = lane >> 2, t2 = (lane & 3) * 2;

    #pragma unroll
    for (int mi = 0; mi < 2; ++mi)
        #pragma unroll
        for (int nf = 0; nf < 4; ++nf) {
            int col = warp_n + nf*8 + t2;
            #pragma unroll
            for (int h = 0; h < 2; ++h) {
                int row = warp_m + mi*16 + g + h*8;
                ob[row*65 + col]     = acc[mi][nf][2*h];
                ob[row*65 + col + 1] = acc[mi][nf][2*h+1];
            }
        }
    __syncthreads();

    if (tid < 64) {
        float s = 0.f;
        #pragma unroll 8
        for (int r = 0; r < 128; ++r) s += ob[r*65 + tid];
        float mean = s * (1.f/128.f);
        float v = 0.f;
        #pragma unroll 8
        for (int r = 0; r < 128; ++r) { float d = ob[r*65 + tid] - mean; v += d*d; }
        smean[tid] = mean;
        sistd[tid] = rsqrtf(v * (1.f/128.f) + 1e-5f);
    }
    __syncthreads();

    const int slot = blockIdx.x * 2 + (wid & 1);
    #pragma unroll
    for (int mi = 0; mi < 2; ++mi) {
        #pragma unroll
        for (int h = 0; h < 2; ++h) {
            int row = warp_m + mi*16 + g + h*8;
            float rsq = 0.f;
            #pragma unroll
            for (int nf = 0; nf < 4; ++nf) {
                int col = warp_n + nf*8 + t2;
                float o0 = acc[mi][nf][2*h], o1 = acc[mi][nf][2*h+1];
                *reinterpret_cast<float2*>(
                    out1 + (size_t)row*(NBINS*OUT) + n*OUT + n0 + col) = make_float2(o0, o1);
                float b0 = gamma[n*OUT + n0 + col]   * (o0 - smean[col])   * sistd[col]   + beta[n*OUT + n0 + col];
                float b1 = gamma[n*OUT + n0 + col+1] * (o1 - smean[col+1]) * sistd[col+1] + beta[n*OUT + n0 + col+1];
                size_t bo = (size_t)n*BATCH*OUT + (size_t)row*OUT + n0 + col;
                *reinterpret_cast<unsigned*>(g_bn + bo) = pack2h(b0, b1);
                rsq += b0*b0 + b1*b1;
            }
            rsq += __shfl_xor_sync(0xffffffffu, rsq, 1);
            rsq += __shfl_xor_sync(0xffffffffu, rsq, 2);
            if ((lane & 3) == 0) g_rowsq[slot][n*BATCH + row] = rsq;
        }
    }
}

// K5c: inverse row norms from 8 partials.
__global__ __launch_bounds__(256) void k5c_rn() {
    int idx = blockIdx.x * 256 + threadIdx.x;
    if (idx < NB) {
        float s = 0.f;
        #pragma unroll
        for (int j = 0; j < 8; ++j) s += g_rowsq[j][idx];
        g_invrn[idx] = 1.f / fmaxf(sqrtf(s), 1e-12f);
    }
}

// =====================================================================
// K6 (fp16 single-pass, pipelined): logits = (bn @ fc1d) * invrow * invcol
// =====================================================================
#define K6_CSQ   (ATILE + BTILE)             // 53248
#define K6_INV   (K6_CSQ + 16*64*4)          // 57344
#define K6_SMEM  (K6_INV + 64*4)             // 57600

__global__ __launch_bounds__(256, 2) void k6_mma(const float* __restrict__ fc,
                                                 float* __restrict__ out2) {
    extern __shared__ char smem[];
    const int n  = blockIdx.y;
    const int n0 = blockIdx.x * 64;
    const int tid = threadIdx.x;
    const int lane = tid & 31, wid = tid >> 5;
    const int warp_m = (wid >> 1) * 32, warp_n = (wid & 1) * 32;
    const uint32_t sb = smem_u32(smem);
    const uint32_t sA = sb, sB = sb + ATILE;

    const __half* A = g_bn + (size_t)n*BATCH*OUT;
    const float* Bg = fc + (size_t)n*OUT*NCLS;

    float acc[2][4][4];
    #pragma unroll
    for (int mi = 0; mi < 2; ++mi)
        #pragma unroll
        for (int nf = 0; nf < 4; ++nf)
            #pragma unroll
            for (int j = 0; j < 4; ++j) acc[mi][nf][j] = 0.f;

    const int cg = (tid & 15) * 4;
    const int kr = tid >> 4;
    const int arow = tid >> 4, ac8 = (tid & 15) * 8;
    const bool valid = (n0 + cg) < NCLS;
    float sq0 = 0.f, sq1 = 0.f, sq2 = 0.f, sq3 = 0.f;

    float4 rB[8];
    #pragma unroll
    for (int i = 0; i < 8; ++i)
        rB[i] = valid ? *reinterpret_cast<const float4*>(
                            Bg + (size_t)(kr + i*16)*NCLS + n0 + cg)
                      : make_float4(0.f, 0.f, 0.f, 0.f);

    for (int kc = 0; kc < 2; ++kc) {
        #pragma unroll
        for (int i = 0; i < 8; ++i) {
            int row = arow + i*16;
            cpa16(sA + (uint32_t)(row*LDA + ac8) * 2,
                  A + (size_t)row*OUT + kc*128 + ac8);
        }
        CPA_COMMIT();
        #pragma unroll
        for (int i = 0; i < 8; ++i) {
            float4 v = rB[i];
            sq0 += v.x*v.x; sq1 += v.y*v.y; sq2 += v.z*v.z; sq3 += v.w*v.w;
            int o = ((kr + i*16)*LDB + cg) * 2;
            *reinterpret_cast<unsigned long long*>(smem + ATILE + o) =
                pack4h(v.x, v.y, v.z, v.w);
        }
        CPA_WAIT0();
        __syncthreads();
        if (kc == 0) {
            #pragma unroll
            for (int i = 0; i < 8; ++i)
                rB[i] = valid ? *reinterpret_cast<const float4*>(
                                    Bg + (size_t)(128 + kr + i*16)*NCLS + n0 + cg)
                              : make_float4(0.f, 0.f, 0.f, 0.f);
        }
        mma_tile1<2,4>(sA, sB, lane, warp_m, warp_n, acc);
        __syncthreads();
    }

    // column inv-norms
    float* csq = reinterpret_cast<float*>(smem + K6_CSQ);
    *reinterpret_cast<float4*>(csq + kr*64 + cg) = make_float4(sq0, sq1, sq2, sq3);
    __syncthreads();
    float* inv = reinterpret_cast<float*>(smem + K6_INV);
    if (tid < 64) {
        float ss = 0.f;
        #pragma unroll
        for (int r = 0; r < 16; ++r) ss += csq[r*64 + tid];
        inv[tid] = 1.f / fmaxf(sqrtf(ss), 1e-12f);
    }
    __syncthreads();

    const int g = lane >> 2, t2 = (lane & 3) * 2;
    #pragma unroll
    for (int mi = 0; mi < 2; ++mi) {
        #pragma unroll
        for (int nf = 0; nf < 4; ++nf) {
            int col = warp_n + nf*8 + t2;
            if (n0 + col >= NCLS) continue;
            float ic0 = inv[col], ic1 = inv[col+1];
            #pragma unroll
            for (int h = 0; h < 2; ++h) {
                int row = warp_m + mi*16 + g + h*8;
                float ir = g_invrn[n*BATCH + row];
                *reinterpret_cast<float2*>(
                    out2 + (size_t)row*(NBINS*NCLS) + n*NCLS + n0 + col) =
                    make_float2(acc[mi][nf][2*h]*ir*ic0, acc[mi][nf][2*h+1]*ir*ic1);
            }
        }
    }
}

// =====================================================================
extern "C" void kernel_launch(void* const* d_in, const int* in_sizes, int n_in,
                              void* d_out, int out_size) {
    const float* x     = (const float*)d_in[0];
    const float* Wmask = (const float*)d_in[1];
    const float* Wout  = (const float*)d_in[2];
    const float* FF    = (const float*)d_in[3];
    const float* gamma = (const float*)d_in[4];
    const float* beta  = (const float*)d_in[5];
    const float* fc1d  = (const float*)d_in[6];
    float* out  = (float*)d_out;
    float* out1 = out;                                   // [128,31,256]
    float* out2 = out + (size_t)BATCH*NBINS*OUT;         // [128,31,10000]

    cudaFuncSetAttribute(k2_mask, cudaFuncAttributeMaxDynamicSharedMemorySize, K2_SMEM);
    cudaFuncSetAttribute(k3_mma, cudaFuncAttributeMaxDynamicSharedMemorySize, K3_SMEM);
    cudaFuncSetAttribute(k4_ff,  cudaFuncAttributeMaxDynamicSharedMemorySize, K4_SMEM);
    cudaFuncSetAttribute(k6_mma, cudaFuncAttributeMaxDynamicSharedMemorySize, K6_SMEM);

    k1_hmap<<<BATCH*TT*8, 512>>>(x);
    k2_mask<<<NB, 256, K2_SMEM>>>(Wmask);
    k3_mma<<<dim3(4, NBINS, 2), 256, K3_SMEM>>>(Wout);
    k3e_epi<<<992, 256>>>();
    k4_ff<<<dim3(4, NBINS), 256, K4_SMEM>>>(FF, gamma, beta, out1);
    k5c_rn<<<(NB + 255) / 256, 256>>>();
    k6_mma<<<dim3((NCLS + 63) / 64, NBINS), 256, K6_SMEM>>>(fc1d, out2);
}

// round 11
// speedup vs baseline: 1.3933x; 1.3933x over previous
#include <cuda_runtime.h>
#include <cuda_fp16.h>
#include <cstdint>

// ---------------- problem constants ----------------
#define BATCH 128
#define CH    256
#define TT    30
#define WW    11
#define HW    176
#define NBINS 31
#define RED   16
#define KDIM  4096
#define OUT   256
#define NCLS  10000
#define NB    (NBINS*BATCH)
#define SPLITK 4

#define LDA   136   // GEMM A smem row stride (fp16)
#define LDB   72    // GEMM B smem row stride (fp16)

// ---------------- scratch ----------------
__device__ float g_p[(size_t)NBINS*BATCH*TT*CH];
__device__ float g_pmax[NBINS*BATCH*CH];
__device__ __half g_pooled_hi[(size_t)NBINS*BATCH*KDIM];
__device__ __half g_pooled_lo[(size_t)NBINS*BATCH*KDIM];
__device__ __half g_feat_hi[NBINS*BATCH*CH];
__device__ __half g_feat_lo[NBINS*BATCH*CH];
__device__ __half g_bn[NBINS*BATCH*OUT];                   // fp16 single
__device__ float g_invrn[NB];
__device__ float g_rowsq[8][NB];
__device__ float g_part[(size_t)SPLITK*NBINS*BATCH*OUT];

// ---------------- helpers ----------------
__device__ __forceinline__ uint32_t smem_u32(const void* p) {
    uint32_t a;
    asm("{ .reg .u64 t; cvta.to.shared.u64 t, %1; cvt.u32.u64 %0, t; }" : "=r"(a) : "l"(p));
    return a;
}
__device__ __forceinline__ void cpa16(uint32_t dst, const void* src) {
    asm volatile("cp.async.cg.shared.global [%0], [%1], 16;" :: "r"(dst), "l"(src));
}
#define CPA_COMMIT() asm volatile("cp.async.commit_group;" ::: "memory")
#define CPA_WAIT0()  asm volatile("cp.async.wait_group 0;" ::: "memory")

__device__ __forceinline__ void ldsm4(uint32_t a[4], uint32_t addr) {
    asm volatile("ldmatrix.sync.aligned.m8n8.x4.shared.b16 {%0,%1,%2,%3}, [%4];"
        : "=r"(a[0]),"=r"(a[1]),"=r"(a[2]),"=r"(a[3]) : "r"(addr));
}
__device__ __forceinline__ void ldsm4t(uint32_t a[4], uint32_t addr) {
    asm volatile("ldmatrix.sync.aligned.m8n8.x4.trans.shared.b16 {%0,%1,%2,%3}, [%4];"
        : "=r"(a[0]),"=r"(a[1]),"=r"(a[2]),"=r"(a[3]) : "r"(addr));
}
__device__ __forceinline__ void mma_f16(float d[4], const uint32_t a[4], uint32_t b0, uint32_t b1) {
    asm volatile("mma.sync.aligned.m16n8k16.row.col.f32.f16.f16.f32 "
        "{%0,%1,%2,%3}, {%4,%5,%6,%7}, {%8,%9}, {%0,%1,%2,%3};"
        : "+f"(d[0]),"+f"(d[1]),"+f"(d[2]),"+f"(d[3])
        : "r"(a[0]),"r"(a[1]),"r"(a[2]),"r"(a[3]), "r"(b0),"r"(b1));
}
__device__ __forceinline__ unsigned pack2h(float a, float b) {
    __half2 h = __floats2half2_rn(a, b);
    return *reinterpret_cast<unsigned*>(&h);
}
__device__ __forceinline__ unsigned long long pack4h(float a, float b, float c, float d) {
    return ((unsigned long long)pack2h(c, d) << 32) | pack2h(a, b);
}
__device__ __forceinline__ float h_lo(float v) {
    return v - __half2float(__float2half_rn(v));
}

// single-pass fp16 tile step (k6).
template<int MI, int NF>
__device__ __forceinline__ void mma_tile1(uint32_t sA, uint32_t sB,
                                          int lane, int warp_m, int warp_n,
                                          float (&acc)[MI][NF][4]) {
    const int l15 = lane & 15;
    const int l16 = (lane >> 4) << 3;
    #pragma unroll
    for (int ks = 0; ks < 8; ++ks) {
        const int k = ks * 16;
        uint32_t aa[MI][4], bb[NF][2];
        #pragma unroll
        for (int mi = 0; mi < MI; ++mi)
            ldsm4(aa[mi], sA + ((warp_m + mi*16 + l15)*LDA + k + l16) * 2);
        #pragma unroll
        for (int q = 0; q < NF/2; ++q) {
            uint32_t r[4];
            ldsm4t(r, sB + ((k + l15)*LDB + warp_n + q*16 + l16) * 2);
            bb[2*q][0] = r[0]; bb[2*q][1] = r[1];
            bb[2*q+1][0] = r[2]; bb[2*q+1][1] = r[3];
        }
        #pragma unroll
        for (int mi = 0; mi < MI; ++mi)
            #pragma unroll
            for (int nf = 0; nf < NF; ++nf)
                mma_f16(acc[mi][nf], aa[mi], bb[nf][0], bb[nf][1]);
    }
}

// two-pass (A hi/lo) tile step (k3, k4).
template<int MI, int NF>
__device__ __forceinline__ void mma_tile2(uint32_t sAhi, uint32_t sAlo, uint32_t sB,
                                          int lane, int warp_m, int warp_n,
                                          float (&acc)[MI][NF][4]) {
    const int l15 = lane & 15;
    const int l16 = (lane >> 4) << 3;
    #pragma unroll
    for (int ks = 0; ks < 8; ++ks) {
        const int k = ks * 16;
        uint32_t ahi[MI][4], alo[MI][4], bb[NF][2];
        #pragma unroll
        for (int mi = 0; mi < MI; ++mi) {
            uint32_t ao = ((warp_m + mi*16 + l15)*LDA + k + l16) * 2;
            ldsm4(ahi[mi], sAhi + ao);
            ldsm4(alo[mi], sAlo + ao);
        }
        #pragma unroll
        for (int q = 0; q < NF/2; ++q) {
            uint32_t r[4];
            ldsm4t(r, sB + ((k + l15)*LDB + warp_n + q*16 + l16) * 2);
            bb[2*q][0] = r[0]; bb[2*q][1] = r[1];
            bb[2*q+1][0] = r[2]; bb[2*q+1][1] = r[3];
        }
        #pragma unroll
        for (int mi = 0; mi < MI; ++mi)
            #pragma unroll
            for (int nf = 0; nf < NF; ++nf) {
                mma_f16(acc[mi][nf], ahi[mi], bb[nf][0], bb[nf][1]);
                mma_f16(acc[mi][nf], alo[mi], bb[nf][0], bb[nf][1]);
            }
    }
}

// =====================================================================
// K1: horizontal strip pooling.
// =====================================================================
__global__ __launch_bounds__(512) void k1_hmap(const float* __restrict__ x) {
    int bid = blockIdx.x;
    int cg = bid & 7;
    int t  = (bid >> 3) % TT;
    int b  = bid / (TT * 8);

    __shared__ float xs[32][180];
    __shared__ float rsum[32][16];
    __shared__ float rmax[32][16];

    const float* xb = x + (((size_t)b*CH + cg*32)*TT + t) * HW;
    int tid = threadIdx.x;

    for (int idx = tid; idx < 32*44; idx += 512) {
        int c = idx / 44, e = idx % 44;
        float4 v = *reinterpret_cast<const float4*>(xb + (size_t)c*TT*HW + e*4);
        *reinterpret_cast<float4*>(&xs[c][e*4]) = v;
    }
    __syncthreads();
    {
        int c = tid >> 4, h = tid & 15;
        float s = 0.f, m = -1e30f;
        #pragma unroll
        for (int w = 0; w < WW; ++w) {
            float v = xs[c][h*WW + w];
            s += v; m = fmaxf(m, v);
        }
        rsum[c][h] = s; rmax[c][h] = m;
    }
    __syncthreads();

    for (int oi = tid; oi < NBINS*32; oi += 512) {
        int n = oi >> 5;
        int c = oi & 31;
        int start, len;
        if      (n == 0) { start = 0;          len = 16; }
        else if (n < 3)  { start = (n-1)*8;    len = 8;  }
        else if (n < 7)  { start = (n-3)*4;    len = 4;  }
        else if (n < 15) { start = (n-7)*2;    len = 2;  }
        else             { start = n-15;       len = 1;  }
        float s = 0.f, m = -1e30f;
        for (int h = 0; h < len; ++h) {
            s += rsum[c][start+h];
            m = fmaxf(m, rmax[c][start+h]);
        }
        g_p[(((size_t)n*BATCH + b)*TT + t)*CH + cg*32 + c] = s / (float)(len*WW) + m;
    }
}

// =====================================================================
// K2: mask logits (wmsT transposed, float4 LDS) + softmax + pooling.
// Pooled stored as fp16 hi/lo. Dynamic smem: ps | wmsT | lg.
// =====================================================================
#define LDWT 260
#define K2_SMEM (TT*CH*4 + 16*LDWT*4 + TT*RED*4)   // 49280

__global__ __launch_bounds__(512) void k2_mask(const float* __restrict__ Wmask) {
    extern __shared__ float sm[];
    float* ps   = sm;                    // [30][256] flat
    float* wmsT = sm + TT*CH;            // [16][LDWT]
    float* lg   = wmsT + 16*LDWT;        // [30][16] flat

    int nb = blockIdx.x;
    int n = nb >> 7;
    int b = nb & 127;
    int tid = threadIdx.x;

    const float* pg = g_p + ((size_t)n*BATCH + b)*TT*CH;
    for (int i = tid; i < TT*CH/4; i += 512) {
        float4 v = *reinterpret_cast<const float4*>(pg + i*4);
        *reinterpret_cast<float4*>(ps + i*4) = v;
    }
    const float* wg = Wmask + (size_t)n*CH*RED;
    for (int i = tid; i < CH*RED; i += 512) {
        int r = i >> 8, c = i & 255;     // r covers 0..15 across iterations
        wmsT[r*LDWT + c] = wg[c*RED + r];
    }
    __syncthreads();

    // logits [30,16]: thread = (t, r); float4 dual loads
    if (tid < TT*RED) {
        int t = tid >> 4, r = tid & 15;
        const float* pr = ps + t*CH;
        const float* wr = wmsT + r*LDWT;
        float acc = 0.f;
        #pragma unroll 8
        for (int c = 0; c < CH; c += 4) {
            float4 pv = *reinterpret_cast<const float4*>(pr + c);
            float4 wv = *reinterpret_cast<const float4*>(wr + c);
            acc += pv.x*wv.x + pv.y*wv.y + pv.z*wv.z + pv.w*wv.w;
        }
        lg[t*16 + r] = acc;
    }
    __syncthreads();

    // softmax over T per column r
    if (tid < RED) {
        int r = tid;
        float m = -1e30f;
        for (int t = 0; t < TT; ++t) m = fmaxf(m, lg[t*16 + r]);
        float s = 0.f;
        for (int t = 0; t < TT; ++t) { float e = expf(lg[t*16 + r] - m); lg[t*16 + r] = e; s += e; }
        float inv = 1.f / s;
        for (int t = 0; t < TT; ++t) lg[t*16 + r] *= inv;
    }
    __syncthreads();

    // pooled[c][r] (hi/lo fp16) + pmax[c]; thread = (c, half of r)
    {
        int c = tid & 255;
        int rh = tid >> 8;
        float acc[8];
        #pragma unroll
        for (int r = 0; r < 8; ++r) acc[r] = 0.f;
        float pm = -1e30f;
        for (int t = 0; t < TT; ++t) {
            float pv = ps[t*CH + c];
            pm = fmaxf(pm, pv);
            float4 m0 = *reinterpret_cast<const float4*>(lg + t*16 + rh*8);
            float4 m1 = *reinterpret_cast<const float4*>(lg + t*16 + rh*8 + 4);
            acc[0] += pv*m0.x; acc[1] += pv*m0.y; acc[2] += pv*m0.z; acc[3] += pv*m0.w;
            acc[4] += pv*m1.x; acc[5] += pv*m1.y; acc[6] += pv*m1.z; acc[7] += pv*m1.w;
        }
        size_t base = ((size_t)n*BATCH + b)*KDIM + c*RED + rh*8;
        float lo[8];
        #pragma unroll
        for (int r = 0; r < 8; ++r) lo[r] = h_lo(acc[r]);
        unsigned long long* dh = reinterpret_cast<unsigned long long*>(g_pooled_hi + base);
        unsigned long long* dl = reinterpret_cast<unsigned long long*>(g_pooled_lo + base);
        dh[0] = pack4h(acc[0],acc[1],acc[2],acc[3]); dh[1] = pack4h(acc[4],acc[5],acc[6],acc[7]);
        dl[0] = pack4h(lo[0],lo[1],lo[2],lo[3]);     dl[1] = pack4h(lo[4],lo[5],lo[6],lo[7]);
        if (rh == 0) g_pmax[((size_t)n*BATCH + b)*CH + c] = pm;
    }
}

// =====================================================================
// K3 (fp16x2 A, split-K=4, pipelined): partial = pooled @ Wout
// BM=128, BN=64. grid (4 N, NBINS, 4 Ksplit) = 496 CTAs, occ 2.
// =====================================================================
#define ATILE (128*LDA*2)          // 34816
#define BTILE (128*LDB*2)          // 18432
#define K3_SMEM  (2*ATILE + BTILE) // 88064

__global__ __launch_bounds__(256, 2) void k3_mma(const float* __restrict__ Wout) {
    extern __shared__ char smem[];
    const int n    = blockIdx.y;
    const int n0   = blockIdx.x * 64;
    const int ksp  = blockIdx.z;
    const int kbase = ksp * (KDIM / SPLITK);   // 1024
    const int tid = threadIdx.x;
    const int lane = tid & 31, wid = tid >> 5;
    const int warp_m = (wid >> 1) * 32, warp_n = (wid & 1) * 32;
    const uint32_t sb = smem_u32(smem);
    const uint32_t sAhi = sb, sAlo = sb + ATILE, sB = sb + 2*ATILE;

    const __half* Ah = g_pooled_hi + (size_t)n*BATCH*KDIM;
    const __half* Al = g_pooled_lo + (size_t)n*BATCH*KDIM;
    const float* B = Wout + (size_t)n*KDIM*OUT;

    float acc[2][4][4];
    #pragma unroll
    for (int mi = 0; mi < 2; ++mi)
        #pragma unroll
        for (int nf = 0; nf < 4; ++nf)
            #pragma unroll
            for (int j = 0; j < 4; ++j) acc[mi][nf][j] = 0.f;

    const int cg = (tid & 15) * 4;
    const int kr = tid >> 4;
    const int arow = tid >> 4, ac8 = (tid & 15) * 8;

    float4 rB[8];
    #pragma unroll
    for (int i = 0; i < 8; ++i)
        rB[i] = *reinterpret_cast<const float4*>(B + (size_t)(kbase + kr + i*16)*OUT + n0 + cg);

    const int NC = (KDIM / SPLITK) / 128;      // 8
    for (int kc = 0; kc < NC; ++kc) {
        #pragma unroll
        for (int i = 0; i < 8; ++i) {
            int row = arow + i*16;
            size_t gA = (size_t)row*KDIM + kbase + kc*128 + ac8;
            uint32_t so = (uint32_t)(row*LDA + ac8) * 2;
            cpa16(sAhi + so, Ah + gA);
            cpa16(sAlo + so, Al + gA);
        }
        CPA_COMMIT();
        #pragma unroll
        for (int i = 0; i < 8; ++i) {
            float4 v = rB[i];
            int o = ((kr + i*16)*LDB + cg) * 2;
            *reinterpret_cast<unsigned long long*>(smem + 2*ATILE + o) =
                pack4h(v.x, v.y, v.z, v.w);
        }
        CPA_WAIT0();
        __syncthreads();
        if (kc + 1 < NC) {
            #pragma unroll
            for (int i = 0; i < 8; ++i)
                rB[i] = *reinterpret_cast<const float4*>(
                    B + (size_t)(kbase + (kc+1)*128 + kr + i*16)*OUT + n0 + cg);
        }
        mma_tile2<2,4>(sAhi, sAlo, sB, lane, warp_m, warp_n, acc);
        __syncthreads();
    }

    float* pp = g_part + ((size_t)ksp*NBINS + n)*BATCH*OUT;
    const int g = lane >> 2, t2 = (lane & 3) * 2;
    #pragma unroll
    for (int mi = 0; mi < 2; ++mi) {
        #pragma unroll
        for (int nf = 0; nf < 4; ++nf) {
            int col = n0 + warp_n + nf*8 + t2;
            #pragma unroll
            for (int h = 0; h < 2; ++h) {
                int row = warp_m + mi*16 + g + h*8;
                *reinterpret_cast<float2*>(pp + (size_t)row*OUT + col) =
                    make_float2(acc[mi][nf][2*h], acc[mi][nf][2*h+1]);
            }
        }
    }
}

// K3 epilogue: feat = pmax + leaky(sum of 4 partials) -> fp16 hi/lo.
__global__ __launch_bounds__(256) void k3e_epi() {
    int i4 = blockIdx.x * 256 + threadIdx.x;   // < 253952
    const size_t STR = (size_t)NBINS*BATCH*OUT / 4;   // float4 units per split
    const float4* p0 = reinterpret_cast<const float4*>(g_part);
    const float4* pm = reinterpret_cast<const float4*>(g_pmax);
    float4 a = p0[i4], b = p0[STR + i4], c = p0[2*STR + i4], d = p0[3*STR + i4];
    float4 m = pm[i4];
    float o[4];
    float s;
    s = a.x + b.x + c.x + d.x; o[0] = ((s >= 0.f) ? s : 0.01f*s) + m.x;
    s = a.y + b.y + c.y + d.y; o[1] = ((s >= 0.f) ? s : 0.01f*s) + m.y;
    s = a.z + b.z + c.z + d.z; o[2] = ((s >= 0.f) ? s : 0.01f*s) + m.z;
    s = a.w + b.w + c.w + d.w; o[3] = ((s >= 0.f) ? s : 0.01f*s) + m.w;
    reinterpret_cast<unsigned long long*>(g_feat_hi)[i4] = pack4h(o[0], o[1], o[2], o[3]);
    reinterpret_cast<unsigned long long*>(g_feat_lo)[i4] =
        pack4h(h_lo(o[0]), h_lo(o[1]), h_lo(o[2]), h_lo(o[3]));
}

// =====================================================================
// K4 (fp16x2 + fused BatchNorm): outputs = feat @ FForward.
// =====================================================================
#define K4_SMEM  (2*ATILE + BTILE)     // 88064

__global__ __launch_bounds__(256, 2) void k4_ff(const float* __restrict__ FF,
                                                const float* __restrict__ gamma,
                                                const float* __restrict__ beta,
                                                float* __restrict__ out1) {
    extern __shared__ char smem[];
    const int n  = blockIdx.y;
    const int n0 = blockIdx.x * 64;
    const int tid = threadIdx.x;
    const int lane = tid & 31, wid = tid >> 5;
    const int warp_m = (wid >> 1) * 32, warp_n = (wid & 1) * 32;
    const uint32_t sb = smem_u32(smem);
    const uint32_t sAhi = sb, sAlo = sb + ATILE, sB = sb + 2*ATILE;

    const __half* Ah = g_feat_hi + (size_t)n*BATCH*CH;
    const __half* Al = g_feat_lo + (size_t)n*BATCH*CH;
    const float* B = FF + (size_t)n*CH*OUT;

    float acc[2][4][4];
    #pragma unroll
    for (int mi = 0; mi < 2; ++mi)
        #pragma unroll
        for (int nf = 0; nf < 4; ++nf)
            #pragma unroll
            for (int j = 0; j < 4; ++j) acc[mi][nf][j] = 0.f;

    const int cg = (tid & 15) * 4;
    const int kr = tid >> 4;
    const int arow = tid >> 4, ac8 = (tid & 15) * 8;

    float4 rB[8];
    #pragma unroll
    for (int i = 0; i < 8; ++i)
        rB[i] = *reinterpret_cast<const float4*>(B + (size_t)(kr + i*16)*OUT + n0 + cg);

    for (int kc = 0; kc < 2; ++kc) {
        #pragma unroll
        for (int i = 0; i < 8; ++i) {
            int row = arow + i*16;
            size_t gA = (size_t)row*CH + kc*128 + ac8;
            uint32_t so = (uint32_t)(row*LDA + ac8) * 2;
            cpa16(sAhi + so, Ah + gA);
            cpa16(sAlo + so, Al + gA);
        }
        CPA_COMMIT();
        #pragma unroll
        for (int i = 0; i < 8; ++i) {
            float4 v = rB[i];
            int o = ((kr + i*16)*LDB + cg) * 2;
            *reinterpret_cast<unsigned long long*>(smem + 2*ATILE + o) =
                pack4h(v.x, v.y, v.z, v.w);
        }
        CPA_WAIT0();
        __syncthreads();
        if (kc == 0) {
            #pragma unroll
            for (int i = 0; i < 8; ++i)
                rB[i] = *reinterpret_cast<const float4*>(
                    B + (size_t)(128 + kr + i*16)*OUT + n0 + cg);
        }
        mma_tile2<2,4>(sAhi, sAlo, sB, lane, warp_m, warp_n, acc);
        __syncthreads();
    }

    // ---- fused BatchNorm epilogue ----
    float* ob = reinterpret_cast<float*>(smem);        // [128][65]
    float* smean = ob + 128*65;
    float* sistd = smean + 64;
    const int g = lane >> 2, t2 = (lane & 3) * 2;

    #pragma unroll
    for (int mi = 0; mi < 2; ++mi)
        #pragma unroll
        for (int nf = 0; nf < 4; ++nf) {
            int col = warp_n + nf*8 + t2;
            #pragma unroll
            for (int h = 0; h < 2; ++h) {
                int row = warp_m + mi*16 + g + h*8;
                ob[row*65 + col]     = acc[mi][nf][2*h];
                ob[row*65 + col + 1] = acc[mi][nf][2*h+1];
            }
        }
    __syncthreads();

    if (tid < 64) {
        float s = 0.f;
        #pragma unroll 8
        for (int r = 0; r < 128; ++r) s += ob[r*65 + tid];
        float mean = s * (1.f/128.f);
        float v = 0.f;
        #pragma unroll 8
        for (int r = 0; r < 128; ++r) { float d = ob[r*65 + tid] - mean; v += d*d; }
        smean[tid] = mean;
        sistd[tid] = rsqrtf(v * (1.f/128.f) + 1e-5f);
    }
    __syncthreads();

    const int slot = blockIdx.x * 2 + (wid & 1);
    #pragma unroll
    for (int mi = 0; mi < 2; ++mi) {
        #pragma unroll
        for (int h = 0; h < 2; ++h) {
            int row = warp_m + mi*16 + g + h*8;
            float rsq = 0.f;
            #pragma unroll
            for (int nf = 0; nf < 4; ++nf) {
                int col = warp_n + nf*8 + t2;
                float o0 = acc[mi][nf][2*h], o1 = acc[mi][nf][2*h+1];
                *reinterpret_cast<float2*>(
                    out1 + (size_t)row*(NBINS*OUT) + n*OUT + n0 + col) = make_float2(o0, o1);
                float b0 = gamma[n*OUT + n0 + col]   * (o0 - smean[col])   * sistd[col]   + beta[n*OUT + n0 + col];
                float b1 = gamma[n*OUT + n0 + col+1] * (o1 - smean[col+1]) * sistd[col+1] + beta[n*OUT + n0 + col+1];
                size_t bo = (size_t)n*BATCH*OUT + (size_t)row*OUT + n0 + col;
                *reinterpret_cast<unsigned*>(g_bn + bo) = pack2h(b0, b1);
                rsq += b0*b0 + b1*b1;
            }
            rsq += __shfl_xor_sync(0xffffffffu, rsq, 1);
            rsq += __shfl_xor_sync(0xffffffffu, rsq, 2);
            if ((lane & 3) == 0) g_rowsq[slot][n*BATCH + row] = rsq;
        }
    }
}

// K5c: inverse row norms from 8 partials.
__global__ __launch_bounds__(256) void k5c_rn() {
    int idx = blockIdx.x * 256 + threadIdx.x;
    if (idx < NB) {
        float s = 0.f;
        #pragma unroll
        for (int j = 0; j < 8; ++j) s += g_rowsq[j][idx];
        g_invrn[idx] = 1.f / fmaxf(sqrtf(s), 1e-12f);
    }
}

// =====================================================================
// K6 (fp16 single-pass, pipelined): logits = (bn @ fc1d) * invrow * invcol
// =====================================================================
#define K6_CSQ   (ATILE + BTILE)             // 53248
#define K6_INV   (K6_CSQ + 16*64*4)          // 57344
#define K6_SMEM  (K6_INV + 64*4)             // 57600

__global__ __launch_bounds__(256, 2) void k6_mma(const float* __restrict__ fc,
                                                 float* __restrict__ out2) {
    extern __shared__ char smem[];
    const int n  = blockIdx.y;
    const int n0 = blockIdx.x * 64;
    const int tid = threadIdx.x;
    const int lane = tid & 31, wid = tid >> 5;
    const int warp_m = (wid >> 1) * 32, warp_n = (wid & 1) * 32;
    const uint32_t sb = smem_u32(smem);
    const uint32_t sA = sb, sB = sb + ATILE;

    const __half* A = g_bn + (size_t)n*BATCH*OUT;
    const float* Bg = fc + (size_t)n*OUT*NCLS;

    float acc[2][4][4];
    #pragma unroll
    for (int mi = 0; mi < 2; ++mi)
        #pragma unroll
        for (int nf = 0; nf < 4; ++nf)
            #pragma unroll
            for (int j = 0; j < 4; ++j) acc[mi][nf][j] = 0.f;

    const int cg = (tid & 15) * 4;
    const int kr = tid >> 4;
    const int arow = tid >> 4, ac8 = (tid & 15) * 8;
    const bool valid = (n0 + cg) < NCLS;
    float sq0 = 0.f, sq1 = 0.f, sq2 = 0.f, sq3 = 0.f;

    float4 rB[8];
    #pragma unroll
    for (int i = 0; i < 8; ++i)
        rB[i] = valid ? *reinterpret_cast<const float4*>(
                            Bg + (size_t)(kr + i*16)*NCLS + n0 + cg)
                      : make_float4(0.f, 0.f, 0.f, 0.f);

    for (int kc = 0; kc < 2; ++kc) {
        #pragma unroll
        for (int i = 0; i < 8; ++i) {
            int row = arow + i*16;
            cpa16(sA + (uint32_t)(row*LDA + ac8) * 2,
                  A + (size_t)row*OUT + kc*128 + ac8);
        }
        CPA_COMMIT();
        #pragma unroll
        for (int i = 0; i < 8; ++i) {
            float4 v = rB[i];
            sq0 += v.x*v.x; sq1 += v.y*v.y; sq2 += v.z*v.z; sq3 += v.w*v.w;
            int o = ((kr + i*16)*LDB + cg) * 2;
            *reinterpret_cast<unsigned long long*>(smem + ATILE + o) =
                pack4h(v.x, v.y, v.z, v.w);
        }
        CPA_WAIT0();
        __syncthreads();
        if (kc == 0) {
            #pragma unroll
            for (int i = 0; i < 8; ++i)
                rB[i] = valid ? *reinterpret_cast<const float4*>(
                                    Bg + (size_t)(128 + kr + i*16)*NCLS + n0 + cg)
                              : make_float4(0.f, 0.f, 0.f, 0.f);
        }
        mma_tile1<2,4>(sA, sB, lane, warp_m, warp_n, acc);
        __syncthreads();
    }

    // column inv-norms
    float* csq = reinterpret_cast<float*>(smem + K6_CSQ);
    *reinterpret_cast<float4*>(csq + kr*64 + cg) = make_float4(sq0, sq1, sq2, sq3);
    __syncthreads();
    float* inv = reinterpret_cast<float*>(smem + K6_INV);
    if (tid < 64) {
        float ss = 0.f;
        #pragma unroll
        for (int r = 0; r < 16; ++r) ss += csq[r*64 + tid];
        inv[tid] = 1.f / fmaxf(sqrtf(ss), 1e-12f);
    }
    __syncthreads();

    const int g = lane >> 2, t2 = (lane & 3) * 2;
    #pragma unroll
    for (int mi = 0; mi < 2; ++mi) {
        #pragma unroll
        for (int nf = 0; nf < 4; ++nf) {
            int col = warp_n + nf*8 + t2;
            if (n0 + col >= NCLS) continue;
            float ic0 = inv[col], ic1 = inv[col+1];
            #pragma unroll
            for (int h = 0; h < 2; ++h) {
                int row = warp_m + mi*16 + g + h*8;
                float ir = g_invrn[n*BATCH + row];
                *reinterpret_cast<float2*>(
                    out2 + (size_t)row*(NBINS*NCLS) + n*NCLS + n0 + col) =
                    make_float2(acc[mi][nf][2*h]*ir*ic0, acc[mi][nf][2*h+1]*ir*ic1);
            }
        }
    }
}

// =====================================================================
extern "C" void kernel_launch(void* const* d_in, const int* in_sizes, int n_in,
                              void* d_out, int out_size) {
    const float* x     = (const float*)d_in[0];
    const float* Wmask = (const float*)d_in[1];
    const float* Wout  = (const float*)d_in[2];
    const float* FF    = (const float*)d_in[3];
    const float* gamma = (const float*)d_in[4];
    const float* beta  = (const float*)d_in[5];
    const float* fc1d  = (const float*)d_in[6];
    float* out  = (float*)d_out;
    float* out1 = out;                                   // [128,31,256]
    float* out2 = out + (size_t)BATCH*NBINS*OUT;         // [128,31,10000]

    cudaFuncSetAttribute(k2_mask, cudaFuncAttributeMaxDynamicSharedMemorySize, K2_SMEM);
    cudaFuncSetAttribute(k3_mma, cudaFuncAttributeMaxDynamicSharedMemorySize, K3_SMEM);
    cudaFuncSetAttribute(k4_ff,  cudaFuncAttributeMaxDynamicSharedMemorySize, K4_SMEM);
    cudaFuncSetAttribute(k6_mma, cudaFuncAttributeMaxDynamicSharedMemorySize, K6_SMEM);

    k1_hmap<<<BATCH*TT*8, 512>>>(x);
    k2_mask<<<NB, 512, K2_SMEM>>>(Wmask);
    k3_mma<<<dim3(4, NBINS, SPLITK), 256, K3_SMEM>>>(Wout);
    k3e_epi<<<992, 256>>>();
    k4_ff<<<dim3(4, NBINS), 256, K4_SMEM>>>(FF, gamma, beta, out1);
    k5c_rn<<<(NB + 255) / 256, 256>>>();
    k6_mma<<<dim3((NCLS + 63) / 64, NBINS), 256, K6_SMEM>>>(fc1d, out2);
}